// round 10
// baseline (speedup 1.0000x reference)
#include <cuda_runtime.h>
#include <cuda_fp16.h>
#include <cstdint>

// ============================================================================
// Problem constants
// ============================================================================
#define B_   4
#define C_   64
#define H_   128
#define W_   128
#define Q_   65536
#define FEAT_N (B_ * H_ * W_ * C_)              // 1,048,576
#define WTOT   (32768 + 3 * 65536 + 2048)       // 231,424
#define NT   8192                               // 128-row tiles total

// ============================================================================
// Device scratch (no cudaMalloc allowed)
// ============================================================================
__device__ __align__(16) __half g_featT[(size_t)FEAT_N];   // [B,H,W,C] fp16
__device__ __align__(16) __half g_w0i[256 * 128];  // [n=256][k=128] (real K=68)
__device__ __align__(16) __half g_w1i[256 * 256];  // [n][k]
__device__ __align__(16) __half g_w2i[256 * 256];
__device__ __align__(16) __half g_w3i[256 * 256];
__device__ __align__(16) __half g_w4i[8 * 256];    // [n=8][k=256] (real N=3)

// ============================================================================
// Fused prep kernel
// ============================================================================
__global__ void prep_all(const float* __restrict__ feat,
                         const float* __restrict__ w0, const float* __restrict__ w1,
                         const float* __restrict__ w2, const float* __restrict__ w3,
                         const float* __restrict__ w4) {
    int o = blockIdx.x * blockDim.x + threadIdx.x;
    if (o < FEAT_N) {
        int c  = o & 63;
        int ix = (o >> 6) & 127;
        int iy = (o >> 13) & 127;
        int b  = o >> 20;
        g_featT[o] = __float2half(feat[(((size_t)b * C_ + c) * H_ + iy) * W_ + ix]);
        return;
    }
    int i = o - FEAT_N;
    if (i < 32768) {                        // W0: [256][128], real K=68
        int n = i >> 7, k = i & 127;
        g_w0i[i] = __float2half(k < 68 ? w0[k * 256 + n] : 0.0f);
    } else if (i < 32768 + 3 * 65536) {     // W1..W3: [256][256]
        int j = i - 32768;
        int l = j >> 16; j &= 65535;
        int n = j >> 8, k = j & 255;
        const float* w = (l == 0) ? w1 : ((l == 1) ? w2 : w3);
        __half* d = (l == 0) ? g_w1i : ((l == 1) ? g_w2i : g_w3i);
        d[j] = __float2half(w[k * 256 + n]);
    } else if (i < WTOT) {                  // W4: [8][256], real N=3
        int j = i - 32768 - 3 * 65536;
        int n = j >> 8, k = j & 255;
        g_w4i[j] = __float2half(n < 3 ? w4[k * 3 + n] : 0.0f);
    }
}

// ============================================================================
// PTX wrappers (baseline PTX, valid at compute_103)
// ============================================================================
__device__ __forceinline__ uint32_t smem_u32(const void* p) {
    uint32_t a;
    asm("{ .reg .u64 t; cvta.to.shared.u64 t, %1; cvt.u32.u64 %0, t; }" : "=r"(a) : "l"(p));
    return a;
}
__device__ __forceinline__ void ldsm_x4(uint32_t* r, uint32_t addr) {
    asm volatile("ldmatrix.sync.aligned.m8n8.x4.shared.b16 {%0,%1,%2,%3}, [%4];"
                 : "=r"(r[0]), "=r"(r[1]), "=r"(r[2]), "=r"(r[3]) : "r"(addr));
}
__device__ __forceinline__ void ldsm_x2(uint32_t* r, uint32_t addr) {
    asm volatile("ldmatrix.sync.aligned.m8n8.x2.shared.b16 {%0,%1}, [%2];"
                 : "=r"(r[0]), "=r"(r[1]) : "r"(addr));
}
__device__ __forceinline__ void stsm_x4(uint32_t addr, uint32_t r0, uint32_t r1,
                                        uint32_t r2, uint32_t r3) {
    asm volatile("stmatrix.sync.aligned.m8n8.x4.shared.b16 [%0], {%1,%2,%3,%4};"
                 :: "r"(addr), "r"(r0), "r"(r1), "r"(r2), "r"(r3) : "memory");
}
__device__ __forceinline__ void mma16816(float* d, const uint32_t* a, const uint32_t* b) {
    asm volatile("mma.sync.aligned.m16n8k16.row.col.f32.f16.f16.f32 "
                 "{%0,%1,%2,%3}, {%4,%5,%6,%7}, {%8,%9}, {%0,%1,%2,%3};"
                 : "+f"(d[0]), "+f"(d[1]), "+f"(d[2]), "+f"(d[3])
                 : "r"(a[0]), "r"(a[1]), "r"(a[2]), "r"(a[3]), "r"(b[0]), "r"(b[1]));
}
__device__ __forceinline__ void cp16(uint32_t dst, const void* src) {
    asm volatile("cp.async.cg.shared.global [%0], [%1], 16;" :: "r"(dst), "l"(src));
}
__device__ __forceinline__ void cp_commit() {
    asm volatile("cp.async.commit_group;" ::: "memory");
}
template <int N> __device__ __forceinline__ void cp_wait() {
    asm volatile("cp.async.wait_group %0;" :: "n"(N) : "memory");
}
__device__ __forceinline__ void barn(int id, int cnt) {
    asm volatile("bar.sync %0, %1;" :: "r"(id), "r"(cnt) : "memory");
}

// ============================================================================
// SMEM layout (dynamic)
// ============================================================================
#define SM_ACT    0
#define SM_P      65536
#define SM_BSL    86016
#define SM_W4     217088
#define SM_BIAS   221184
#define SM_B4     225280
#define SM_AREAA  225296
#define SM_AREAB  225808
#define SM_PRED   226320
#define SMEM_BYTES 227856

// chunk = 16B group of 8 halves; swizzle: chunk' = chunk ^ (row & 7)
__device__ __forceinline__ uint32_t swz(int row, int chunk, int rowshift) {
    return ((uint32_t)row << rowshift) + (uint32_t)((chunk ^ (row & 7)) << 4);
}
// P-buffer addressing: 160B rows, chunks 0..7 swizzled, 8..9 plain
__device__ __forceinline__ uint32_t addrP(int row, int chunk) {
    int c = (chunk < 8) ? (chunk ^ (row & 7)) : chunk;
    return (uint32_t)row * 160u + ((uint32_t)c << 4);
}

// ============================================================================
// Full-layer compute: warp tile 32 rows x 64 cols, K = KT*16.
// A double-buffered in regs, B single-buffered (latency hidden by 4 warps/SMSP).
// ============================================================================
template <int KT, bool FROMP>
__device__ __forceinline__ void compute_full(
    uint32_t abase, uint32_t bslice, const float* bias, int wm, int lane,
    uint32_t (&o01)[2][8], uint32_t (&o23)[2][8])
{
    float acc[2][8][4];
    #pragma unroll
    for (int mt = 0; mt < 2; mt++)
        #pragma unroll
        for (int nt = 0; nt < 8; nt++)
            #pragma unroll
            for (int u = 0; u < 4; u++) acc[mt][nt][u] = 0.0f;

    uint32_t a[2][2][4];
    uint32_t bf[8][2];

    auto ldA = [&](int kt, int s) {
        #pragma unroll
        for (int mt = 0; mt < 2; mt++) {
            int row = wm * 32 + mt * 16 + (lane & 15);
            int ch = kt * 2 + (lane >> 4);
            uint32_t ad = FROMP ? (abase + addrP(row, ch))
                                : (abase + swz(row, ch, 9));
            ldsm_x4(a[s][mt], ad);
        }
    };
    auto ldB = [&](int kt) {
        #pragma unroll
        for (int bt = 0; bt < 4; bt++) {
            uint32_t r4[4];
            ldsm_x4(r4, bslice + swz(bt * 16 + (lane & 7) + ((lane >> 4) << 3),
                                     kt * 2 + ((lane >> 3) & 1), 9));
            bf[2 * bt][0] = r4[0]; bf[2 * bt][1] = r4[1];
            bf[2 * bt + 1][0] = r4[2]; bf[2 * bt + 1][1] = r4[3];
        }
    };

    ldA(0, 0);
    #pragma unroll
    for (int kt = 0; kt < KT; kt++) {
        const int cur = kt & 1;
        ldB(kt);
        if (kt + 1 < KT) ldA(kt + 1, cur ^ 1);
        #pragma unroll
        for (int mt = 0; mt < 2; mt++)
            #pragma unroll
            for (int nt = 0; nt < 8; nt++)
                mma16816(acc[mt][nt], a[cur][mt], bf[nt]);
    }

    #pragma unroll
    for (int mt = 0; mt < 2; mt++)
        #pragma unroll
        for (int nt = 0; nt < 8; nt++) {
            float bb0 = bias[nt * 8 + (lane & 3) * 2];
            float bb1 = bias[nt * 8 + (lane & 3) * 2 + 1];
            float v0 = fmaxf(acc[mt][nt][0] + bb0, 0.0f);
            float v1 = fmaxf(acc[mt][nt][1] + bb1, 0.0f);
            float v2 = fmaxf(acc[mt][nt][2] + bb0, 0.0f);
            float v3 = fmaxf(acc[mt][nt][3] + bb1, 0.0f);
            __half2 p01 = __floats2half2_rn(v0, v1);
            __half2 p23 = __floats2half2_rn(v2, v3);
            o01[mt][nt] = *(uint32_t*)&p01;
            o23[mt][nt] = *(uint32_t*)&p23;
        }
}

// ============================================================================
// Persistent fused MLP kernel: grid = #SMs, 512 threads = 16 warps (wm4 x wn4),
// warp tile 32x64. L4 from L3 registers + smem atomic reduction.
// ============================================================================
__global__ void __launch_bounds__(512, 1) liif_mlp(
    const float* __restrict__ coord, const float* __restrict__ cell,
    const float* __restrict__ b0, const float* __restrict__ b1,
    const float* __restrict__ b2, const float* __restrict__ b3,
    const float* __restrict__ b4, float* __restrict__ out)
{
    extern __shared__ char smem[];
    uint32_t sb = smem_u32(smem);
    const int tid = threadIdx.x;
    const int lane = tid & 31;
    const int wid = tid >> 5;
    const int wm = wid >> 2;       // 4 row groups x 32 rows
    const int wn = wid & 3;        // 4 col groups x 64 cols
    const uint32_t act = sb + SM_ACT;
    const uint32_t P = sb + SM_P;
    const uint32_t bslice = sb + SM_BSL + (uint32_t)wn * 32768;
    const int g = lane >> 3, lr = lane & 7;
    const int GRP = 1 + wm;        // same-wm warps, 128 threads (ids 1..4)
    const int BSL = 5 + wn;        // same-wn warps, 128 threads (ids 5..8)

    // ---- gather prefetch for one tile into P + area buffer (no commit) -----
    auto prefetch_gather = [&](int tile, uint32_t areaOff) {
        int i = tid >> 2, part = tid & 3;      // 4 threads per row
        int r = tile * 128 + i;
        int point = r >> 2, j = r & 3;
        int b = point >> 16, q = point & 65535;
        const float* cp = coord + (size_t)(b * Q_ + q) * 2;
        float c0 = cp[0], c1 = cp[1];
        const float* cl = cell + (size_t)(b * Q_ + q) * 2;
        float rc0 = cl[0] * 128.0f, rc1 = cl[1] * 128.0f;
        const float EPS = 1e-6f, RX = 0.0078125f;
        float sx = ((j & 2) ? RX : -RX) + EPS;
        float sy = ((j & 1) ? RX : -RX) + EPS;
        float lo = -1.0f + EPS, hi = 1.0f - EPS;
        float cs0 = fminf(fmaxf(c0 + sx, lo), hi);
        float cs1 = fminf(fmaxf(c1 + sy, lo), hi);
        int iy = (int)fminf(fmaxf(floorf((cs0 + 1.0f) * 64.0f), 0.0f), 127.0f);
        int ix = (int)fminf(fmaxf(floorf((cs1 + 1.0f) * 64.0f), 0.0f), 127.0f);
        float qc0 = (float)(2 * iy + 1) * 0.0078125f - 1.0f;
        float qc1 = (float)(2 * ix + 1) * 0.0078125f - 1.0f;
        float rel0 = (c0 - qc0) * 128.0f;
        float rel1 = (c1 - qc1) * 128.0f;
        if (part == 0)
            *(float*)(smem + areaOff + i * 4) = fabsf(rel0 * rel1) + 1e-9f;

        const char* fp = (const char*)(g_featT + ((size_t)((b << 14) + (iy << 7) + ix) << 6));
        #pragma unroll
        for (int u = 0; u < 2; u++) {
            int c = part * 2 + u;
            cp16(P + (uint32_t)i * 160u + (uint32_t)((c ^ (i & 7)) << 4), fp + c * 16);
        }
        if (part == 3) {
            __half2 h0 = __floats2half2_rn(rel0, rel1);
            __half2 h1 = __floats2half2_rn(rc0, rc1);
            uint4 v;
            v.x = *(uint32_t*)&h0; v.y = *(uint32_t*)&h1; v.z = 0; v.w = 0;
            *(uint4*)(smem + SM_P + i * 160 + 128) = v;          // chunk 8
        }
    };

    // ---- per-wn weight slice load for layer l (warp-scope, k-quarter split) -
    auto issue_bload = [&](int l) {
        if (l == 0) {
            #pragma unroll 4
            for (int idx = lane; idx < 256; idx += 32) {   // 64 n x 4 chunks
                int n = idx >> 2, c = wm * 4 + (idx & 3);
                cp16(bslice + (uint32_t)n * 512 + (uint32_t)((c ^ (n & 7)) << 4),
                     g_w0i + (size_t)(wn * 64 + n) * 128 + c * 8);
            }
        } else {
            const __half* wsrc = (l == 1) ? g_w1i : (l == 2) ? g_w2i : g_w3i;
            #pragma unroll 4
            for (int idx = lane; idx < 512; idx += 32) {   // 64 n x 8 chunks
                int n = idx >> 3, c = wm * 8 + (idx & 7);
                cp16(bslice + (uint32_t)n * 512 + (uint32_t)((c ^ (n & 7)) << 4),
                     wsrc + (size_t)(wn * 64 + n) * 256 + c * 8);
            }
        }
        cp_commit();
    };

    auto store_out = [&](uint32_t (&o01)[2][8], uint32_t (&o23)[2][8]) {
        #pragma unroll
        for (int mt = 0; mt < 2; mt++)
            #pragma unroll
            for (int np = 0; np < 4; np++) {
                int row = wm * 32 + mt * 16 + ((g & 1) << 3) + lr;
                int chunk = wn * 8 + np * 2 + (g >> 1);
                stsm_x4(act + swz(row, chunk, 9),
                        o01[mt][2 * np], o23[mt][2 * np],
                        o01[mt][2 * np + 1], o23[mt][2 * np + 1]);
            }
    };

    // ---- prologue ----------------------------------------------------------
    prefetch_gather((int)blockIdx.x, SM_AREAA);
    cp_commit();
    if (tid < 256) {   // W4: 8 rows x 32 chunks
        int n = tid >> 5, c = tid & 31;
        cp16(sb + SM_W4 + (uint32_t)n * 512 + (uint32_t)((c ^ (n & 7)) << 4),
             g_w4i + (size_t)n * 256 + c * 8);
    }
    cp_commit();
    issue_bload(0);
    for (int i = tid; i < 1024; i += 512) {
        int l = i >> 8, n = i & 255;
        const float* p = (l == 0) ? b0 : (l == 1) ? b1 : (l == 2) ? b2 : b3;
        *(float*)(smem + SM_BIAS + i * 4) = p[n];
    }
    if (tid < 3) *(float*)(smem + SM_B4 + tid * 4) = b4[tid];
    if (tid < 128) {   // P chunk 9 (constant zero padding) — written once
        uint4 z; z.x = z.y = z.z = z.w = 0;
        *(uint4*)(smem + SM_P + tid * 160 + 144) = z;
    }
    if (tid < 384) ((float*)(smem + SM_PRED))[tid] = 0.0f;
    cp_wait<0>();
    __syncthreads();

    uint32_t areaCur = SM_AREAA, areaNxt = SM_AREAB;
    uint32_t o01[2][8], o23[2][8];
    const float* biasB = (const float*)(smem + SM_BIAS);

    // ---- persistent tile loop ----------------------------------------------
    for (int tile = blockIdx.x; tile < NT; tile += gridDim.x) {
        const int next = tile + gridDim.x;

        // layer 0 (A from P)
        compute_full<5, true>(P, bslice, biasB + wn * 64, wm, lane, o01, o23);
        barn(BSL, 128);                // all 4 wm-warps done reading this slice
        issue_bload(1);
        barn(GRP, 128);                // P + act rows read done within wm-group
        store_out(o01, o23);
        if (next < NT) prefetch_gather(next, areaNxt);
        cp_commit();                   // prefetch group (possibly empty)
        cp_wait<1>();                  // L1 weights done; prefetch may fly
        barn(GRP, 128); barn(BSL, 128);

        // layers 1..2
        #pragma unroll 1
        for (int l = 1; l < 3; l++) {
            compute_full<16, false>(act, bslice, biasB + l * 256 + wn * 64, wm, lane, o01, o23);
            barn(BSL, 128);
            issue_bload(l + 1);
            barn(GRP, 128);
            store_out(o01, o23);
            cp_wait<0>();
            barn(GRP, 128); barn(BSL, 128);
        }

        // layer 3: compute, keep outputs in registers (no act store)
        compute_full<16, false>(act, bslice, biasB + 3 * 256 + wn * 64, wm, lane, o01, o23);
        barn(BSL, 128);
        issue_bload(0);                // refill W0 slice for next tile

        // layer 4 from registers: D-frag == A-frag; B from W4 at k = wn*64..
        {
            float a4[2][4];
            #pragma unroll
            for (int mt = 0; mt < 2; mt++)
                #pragma unroll
                for (int u = 0; u < 4; u++) a4[mt][u] = 0.0f;
            uint32_t bfr[4][2];
            #pragma unroll
            for (int j = 0; j < 4; j++)
                ldsm_x2(bfr[j], sb + SM_W4 + swz(lane & 7, (wn * 4 + j) * 2 + ((lane >> 3) & 1), 9));
            #pragma unroll
            for (int mt = 0; mt < 2; mt++)
                #pragma unroll
                for (int j = 0; j < 4; j++) {
                    uint32_t afr[4] = { o01[mt][2 * j], o23[mt][2 * j],
                                        o01[mt][2 * j + 1], o23[mt][2 * j + 1] };
                    mma16816(a4[mt], afr, bfr[j]);
                }
            // reduce partials over wn via smem atomics (cols 0..2 real)
            float* pred = (float*)(smem + SM_PRED);
            int t4 = lane & 3, g2 = lane >> 2;
            if (t4 == 0) {
                #pragma unroll
                for (int mt = 0; mt < 2; mt++) {
                    int r = wm * 32 + mt * 16 + g2;
                    atomicAdd(&pred[r * 3 + 0], a4[mt][0]);
                    atomicAdd(&pred[r * 3 + 1], a4[mt][1]);
                    atomicAdd(&pred[(r + 8) * 3 + 0], a4[mt][2]);
                    atomicAdd(&pred[(r + 8) * 3 + 1], a4[mt][3]);
                }
            } else if (t4 == 1) {
                #pragma unroll
                for (int mt = 0; mt < 2; mt++) {
                    int r = wm * 32 + mt * 16 + g2;
                    atomicAdd(&pred[r * 3 + 2], a4[mt][0]);
                    atomicAdd(&pred[(r + 8) * 3 + 2], a4[mt][2]);
                }
            }
        }
        __syncthreads();

        // combine: 32 points (b4 folded in: ensemble weights sum to 1)
        if (tid < 32) {
            const float* PR = (const float*)(smem + SM_PRED);
            const float* AR = (const float*)(smem + areaCur);
            const float* B4 = (const float*)(smem + SM_B4);
            int base = tid * 4;
            float a0 = AR[base], a1 = AR[base + 1], a2 = AR[base + 2], a3 = AR[base + 3];
            float inv = 1.0f / (a0 + a1 + a2 + a3);
            size_t point = (size_t)tile * 32 + tid;
            #pragma unroll
            for (int c = 0; c < 3; c++) {
                float v = PR[(base + 0) * 3 + c] * a3 + PR[(base + 1) * 3 + c] * a2 +
                          PR[(base + 2) * 3 + c] * a1 + PR[(base + 3) * 3 + c] * a0;
                out[point * 3 + c] = v * inv + B4[c];
            }
        }
        __syncthreads();

        // zero own group's pred rows (32 rows * 3 = 96 floats per wm group)
        {
            float* pred = (float*)(smem + SM_PRED);
            int i = tid & 127;
            if (i < 96) pred[wm * 96 + i] = 0.0f;
        }
        cp_wait<0>();                  // W0 slice quarters + gather arrived
        __syncthreads();               // visibility: P, pred zero, W0 slice

        uint32_t t = areaCur; areaCur = areaNxt; areaNxt = t;
    }
}

// ============================================================================
// Launch
// ============================================================================
extern "C" void kernel_launch(void* const* d_in, const int* in_sizes, int n_in,
                              void* d_out, int out_size) {
    const float* feat  = (const float*)d_in[0];
    const float* coord = (const float*)d_in[1];
    const float* cell  = (const float*)d_in[2];
    const float* w0 = (const float*)d_in[3];
    const float* b0 = (const float*)d_in[4];
    const float* w1 = (const float*)d_in[5];
    const float* b1 = (const float*)d_in[6];
    const float* w2 = (const float*)d_in[7];
    const float* b2 = (const float*)d_in[8];
    const float* w3 = (const float*)d_in[9];
    const float* b3 = (const float*)d_in[10];
    const float* w4 = (const float*)d_in[11];
    const float* b4 = (const float*)d_in[12];
    float* out = (float*)d_out;

    static int nsm = 0;
    if (nsm == 0) {
        cudaFuncSetAttribute(liif_mlp, cudaFuncAttributeMaxDynamicSharedMemorySize, SMEM_BYTES);
        int dev = 0;
        cudaGetDevice(&dev);
        cudaDeviceGetAttribute(&nsm, cudaDevAttrMultiProcessorCount, dev);
        if (nsm <= 0) nsm = 148;
    }

    prep_all<<<(FEAT_N + WTOT + 255) / 256, 256>>>(feat, w0, w1, w2, w3, w4);
    liif_mlp<<<nsm, 512, SMEM_BYTES>>>(coord, cell, b0, b1, b2, b3, b4, out);
}

// round 17
// speedup vs baseline: 1.0613x; 1.0613x over previous
#include <cuda_runtime.h>
#include <cuda_fp16.h>
#include <cstdint>

// ============================================================================
// Problem constants
// ============================================================================
#define B_   4
#define C_   64
#define H_   128
#define W_   128
#define Q_   65536
#define FEAT_N (B_ * H_ * W_ * C_)              // 1,048,576
#define WTOT   (32768 + 3 * 65536 + 2048)       // 231,424
#define NT   8192                               // 128-row tiles total

// ============================================================================
// Device scratch (no cudaMalloc allowed)
// ============================================================================
__device__ __align__(16) __half g_featT[(size_t)FEAT_N];   // [B,H,W,C] fp16
__device__ __align__(16) __half g_w0i[256 * 128];  // [n=256][k=128] (real K=68)
__device__ __align__(16) __half g_w1i[256 * 256];  // [n][k]
__device__ __align__(16) __half g_w2i[256 * 256];
__device__ __align__(16) __half g_w3i[256 * 256];
__device__ __align__(16) __half g_w4i[8 * 256];    // [n=8][k=256] (real N=3)

// ============================================================================
// Fused prep kernel
// ============================================================================
__global__ void prep_all(const float* __restrict__ feat,
                         const float* __restrict__ w0, const float* __restrict__ w1,
                         const float* __restrict__ w2, const float* __restrict__ w3,
                         const float* __restrict__ w4) {
    int o = blockIdx.x * blockDim.x + threadIdx.x;
    if (o < FEAT_N) {
        int c  = o & 63;
        int ix = (o >> 6) & 127;
        int iy = (o >> 13) & 127;
        int b  = o >> 20;
        g_featT[o] = __float2half(feat[(((size_t)b * C_ + c) * H_ + iy) * W_ + ix]);
        return;
    }
    int i = o - FEAT_N;
    if (i < 32768) {                        // W0: [256][128], real K=68
        int n = i >> 7, k = i & 127;
        g_w0i[i] = __float2half(k < 68 ? w0[k * 256 + n] : 0.0f);
    } else if (i < 32768 + 3 * 65536) {     // W1..W3: [256][256]
        int j = i - 32768;
        int l = j >> 16; j &= 65535;
        int n = j >> 8, k = j & 255;
        const float* w = (l == 0) ? w1 : ((l == 1) ? w2 : w3);
        __half* d = (l == 0) ? g_w1i : ((l == 1) ? g_w2i : g_w3i);
        d[j] = __float2half(w[k * 256 + n]);
    } else if (i < WTOT) {                  // W4: [8][256], real N=3
        int j = i - 32768 - 3 * 65536;
        int n = j >> 8, k = j & 255;
        g_w4i[j] = __float2half(n < 3 ? w4[k * 3 + n] : 0.0f);
    }
}

// ============================================================================
// PTX wrappers (baseline PTX, valid at compute_103)
// ============================================================================
__device__ __forceinline__ uint32_t smem_u32(const void* p) {
    uint32_t a;
    asm("{ .reg .u64 t; cvta.to.shared.u64 t, %1; cvt.u32.u64 %0, t; }" : "=r"(a) : "l"(p));
    return a;
}
__device__ __forceinline__ void ldsm_x4(uint32_t* r, uint32_t addr) {
    asm volatile("ldmatrix.sync.aligned.m8n8.x4.shared.b16 {%0,%1,%2,%3}, [%4];"
                 : "=r"(r[0]), "=r"(r[1]), "=r"(r[2]), "=r"(r[3]) : "r"(addr));
}
__device__ __forceinline__ void ldsm_x2(uint32_t* r, uint32_t addr) {
    asm volatile("ldmatrix.sync.aligned.m8n8.x2.shared.b16 {%0,%1}, [%2];"
                 : "=r"(r[0]), "=r"(r[1]) : "r"(addr));
}
__device__ __forceinline__ void stsm_x4(uint32_t addr, uint32_t r0, uint32_t r1,
                                        uint32_t r2, uint32_t r3) {
    asm volatile("stmatrix.sync.aligned.m8n8.x4.shared.b16 [%0], {%1,%2,%3,%4};"
                 :: "r"(addr), "r"(r0), "r"(r1), "r"(r2), "r"(r3) : "memory");
}
__device__ __forceinline__ void mma16816(float* d, const uint32_t* a, const uint32_t* b) {
    asm volatile("mma.sync.aligned.m16n8k16.row.col.f32.f16.f16.f32 "
                 "{%0,%1,%2,%3}, {%4,%5,%6,%7}, {%8,%9}, {%0,%1,%2,%3};"
                 : "+f"(d[0]), "+f"(d[1]), "+f"(d[2]), "+f"(d[3])
                 : "r"(a[0]), "r"(a[1]), "r"(a[2]), "r"(a[3]), "r"(b[0]), "r"(b[1]));
}
__device__ __forceinline__ void cp16(uint32_t dst, const void* src) {
    asm volatile("cp.async.cg.shared.global [%0], [%1], 16;" :: "r"(dst), "l"(src));
}
__device__ __forceinline__ void cp_commit() {
    asm volatile("cp.async.commit_group;" ::: "memory");
}
template <int N> __device__ __forceinline__ void cp_wait() {
    asm volatile("cp.async.wait_group %0;" :: "n"(N) : "memory");
}
__device__ __forceinline__ void barn(int id, int cnt) {
    asm volatile("bar.sync %0, %1;" :: "r"(id), "r"(cnt) : "memory");
}

// ============================================================================
// SMEM layout (dynamic)
// ============================================================================
#define SM_ACT    0
#define SM_P      65536
#define SM_BSL    86016      // 4 pairs x 2 buffers x 16KB = 128KB
#define SM_W4     217088
#define SM_BIAS   221184
#define SM_B4     225280
#define SM_AREAA  225296
#define SM_AREAB  225808
#define SM_PRED   226320
#define SMEM_BYTES 227856

// chunk = 16B group of 8 halves; swizzle: chunk' = chunk ^ (row & 7)
__device__ __forceinline__ uint32_t swz(int row, int chunk, int rowshift) {
    return ((uint32_t)row << rowshift) + (uint32_t)((chunk ^ (row & 7)) << 4);
}
// P-buffer addressing: 160B rows, chunks 0..7 swizzled, 8..9 plain
__device__ __forceinline__ uint32_t addrP(int row, int chunk) {
    int c = (chunk < 8) ? (chunk ^ (row & 7)) : chunk;
    return (uint32_t)row * 160u + ((uint32_t)c << 4);
}

// ============================================================================
// Half compute: warp tile 64 rows x 32 cols, K = NKT*16, from buffer buf
// (32 n-rows x 512B rows). Produces packed fp16 outputs for 32 cols.
// ============================================================================
template <int NKT, bool FROMP>
__device__ __forceinline__ void compute_half(
    uint32_t abase, uint32_t buf, const float* bias, int wm, int lane,
    uint32_t (&o01)[4][4], uint32_t (&o23)[4][4])
{
    float acc[4][4][4];
    #pragma unroll
    for (int mt = 0; mt < 4; mt++)
        #pragma unroll
        for (int nt = 0; nt < 4; nt++)
            #pragma unroll
            for (int u = 0; u < 4; u++) acc[mt][nt][u] = 0.0f;

    uint32_t a[2][4][4];
    uint32_t bf[4][2];

    auto ldA = [&](int kt, int s) {
        #pragma unroll
        for (int mt = 0; mt < 4; mt++) {
            int row = wm * 64 + mt * 16 + (lane & 15);
            int ch = kt * 2 + (lane >> 4);
            uint32_t ad = FROMP ? (abase + addrP(row, ch))
                                : (abase + swz(row, ch, 9));
            ldsm_x4(a[s][mt], ad);
        }
    };
    auto ldB = [&](int kt) {
        #pragma unroll
        for (int bt = 0; bt < 2; bt++) {
            uint32_t r4[4];
            ldsm_x4(r4, buf + swz(bt * 16 + (lane & 7) + ((lane >> 4) << 3),
                                  kt * 2 + ((lane >> 3) & 1), 9));
            bf[2 * bt][0] = r4[0]; bf[2 * bt][1] = r4[1];
            bf[2 * bt + 1][0] = r4[2]; bf[2 * bt + 1][1] = r4[3];
        }
    };

    ldA(0, 0);
    #pragma unroll
    for (int j = 0; j < NKT; j++) {
        const int cur = j & 1;
        ldB(j);
        if (j + 1 < NKT) ldA(j + 1, cur ^ 1);
        #pragma unroll
        for (int mt = 0; mt < 4; mt++)
            #pragma unroll
            for (int nt = 0; nt < 4; nt++)
                mma16816(acc[mt][nt], a[cur][mt], bf[nt]);
    }

    #pragma unroll
    for (int mt = 0; mt < 4; mt++)
        #pragma unroll
        for (int nt = 0; nt < 4; nt++) {
            float bb0 = bias[nt * 8 + (lane & 3) * 2];
            float bb1 = bias[nt * 8 + (lane & 3) * 2 + 1];
            float v0 = fmaxf(acc[mt][nt][0] + bb0, 0.0f);
            float v1 = fmaxf(acc[mt][nt][1] + bb1, 0.0f);
            float v2 = fmaxf(acc[mt][nt][2] + bb0, 0.0f);
            float v3 = fmaxf(acc[mt][nt][3] + bb1, 0.0f);
            __half2 p01 = __floats2half2_rn(v0, v1);
            __half2 p23 = __floats2half2_rn(v2, v3);
            o01[mt][nt] = *(uint32_t*)&p01;
            o23[mt][nt] = *(uint32_t*)&p23;
        }
}

// ============================================================================
// Persistent fused MLP kernel: 8 warps = wm2 x wn4.
// n-split double-buffered weights: B0 = X half (cols +0..31), B1 = Y (+32..63).
// SAFE schedule: each phase ISSUES the next phase's load first, computes,
// then PAIR + cp_wait<0> (full drain) + PAIR. No partial drains anywhere.
// ============================================================================
__global__ void __launch_bounds__(256, 1) liif_mlp(
    const float* __restrict__ coord, const float* __restrict__ cell,
    const float* __restrict__ b0, const float* __restrict__ b1,
    const float* __restrict__ b2, const float* __restrict__ b3,
    const float* __restrict__ b4, float* __restrict__ out)
{
    extern __shared__ char smem[];
    uint32_t sb = smem_u32(smem);
    const int tid = threadIdx.x;
    const int lane = tid & 31;
    const int wid = tid >> 5;
    const int wm = wid >> 2;       // 2 row groups x 64 rows
    const int wn = wid & 3;        // 4 col groups x 64 cols
    const uint32_t act = sb + SM_ACT;
    const uint32_t P = sb + SM_P;
    const uint32_t bufX = sb + SM_BSL + (uint32_t)wn * 32768;
    const uint32_t bufY = bufX + 16384;
    const int g = lane >> 3, lr = lane & 7;
    const int GRP = 1 + wm;        // 128-thread barriers (ids 1,2)
    const int PAIR = 4 + wn;       // 64-thread barriers (ids 4..7)

    // ---- gather prefetch (cp16s; commit added by caller) --------------------
    auto prefetch_gather = [&](int tile, uint32_t areaOff) {
        int i = tid >> 1, part = tid & 1;
        int r = tile * 128 + i;
        int point = r >> 2, j = r & 3;
        int b = point >> 16, q = point & 65535;
        const float* cp = coord + (size_t)(b * Q_ + q) * 2;
        float c0 = cp[0], c1 = cp[1];
        const float* cl = cell + (size_t)(b * Q_ + q) * 2;
        float rc0 = cl[0] * 128.0f, rc1 = cl[1] * 128.0f;
        const float EPS = 1e-6f, RX = 0.0078125f;
        float sx = ((j & 2) ? RX : -RX) + EPS;
        float sy = ((j & 1) ? RX : -RX) + EPS;
        float lo = -1.0f + EPS, hi = 1.0f - EPS;
        float cs0 = fminf(fmaxf(c0 + sx, lo), hi);
        float cs1 = fminf(fmaxf(c1 + sy, lo), hi);
        int iy = (int)fminf(fmaxf(floorf((cs0 + 1.0f) * 64.0f), 0.0f), 127.0f);
        int ix = (int)fminf(fmaxf(floorf((cs1 + 1.0f) * 64.0f), 0.0f), 127.0f);
        float qc0 = (float)(2 * iy + 1) * 0.0078125f - 1.0f;
        float qc1 = (float)(2 * ix + 1) * 0.0078125f - 1.0f;
        float rel0 = (c0 - qc0) * 128.0f;
        float rel1 = (c1 - qc1) * 128.0f;
        if (part == 0)
            *(float*)(smem + areaOff + i * 4) = fabsf(rel0 * rel1) + 1e-9f;

        const char* fp = (const char*)(g_featT + ((size_t)((b << 14) + (iy << 7) + ix) << 6));
        #pragma unroll
        for (int u = 0; u < 4; u++) {
            int c = part * 4 + u;
            cp16(P + (uint32_t)i * 160u + (uint32_t)((c ^ (i & 7)) << 4), fp + c * 16);
        }
        if (part == 1) {
            __half2 h0 = __floats2half2_rn(rel0, rel1);
            __half2 h1 = __floats2half2_rn(rc0, rc1);
            uint4 v;
            v.x = *(uint32_t*)&h0; v.y = *(uint32_t*)&h1; v.z = 0; v.w = 0;
            *(uint4*)(smem + SM_P + i * 160 + 128) = v;          // chunk 8
        }
    };

    // ---- buffer loaders (32 n-rows x 512B; split across wm by k-half) ------
    auto bload = [&](uint32_t dst, const __half* wsrc, int h) {
        #pragma unroll 4
        for (int idx = lane; idx < 512; idx += 32) {   // 32 n x 16 chunks/warp
            int n = idx >> 4, c = wm * 16 + (idx & 15);
            cp16(dst + (uint32_t)n * 512 + (uint32_t)((c ^ (n & 7)) << 4),
                 wsrc + (size_t)(wn * 64 + h * 32 + n) * 256 + c * 8);
        }
        cp_commit();
    };
    auto bload0 = [&](uint32_t dst, int h) {           // L0: 32 n x 16 chunks
        #pragma unroll 4
        for (int idx = lane; idx < 256; idx += 32) {   // 8 chunks/warp
            int n = idx >> 3, c = wm * 8 + (idx & 7);
            cp16(dst + (uint32_t)n * 512 + (uint32_t)((c ^ (n & 7)) << 4),
                 g_w0i + (size_t)(wn * 64 + h * 32 + n) * 128 + c * 8);
        }
        cp_commit();
    };

    uint32_t oA01[4][4], oA23[4][4], oB01[4][4], oB23[4][4];
    auto store_out = [&]() {
        #pragma unroll
        for (int mt = 0; mt < 4; mt++) {
            int row = wm * 64 + mt * 16 + ((g & 1) << 3) + lr;
            #pragma unroll
            for (int np = 0; np < 2; np++) {
                stsm_x4(act + swz(row, wn * 8 + np * 2 + (g >> 1), 9),
                        oA01[mt][2 * np], oA23[mt][2 * np],
                        oA01[mt][2 * np + 1], oA23[mt][2 * np + 1]);
                stsm_x4(act + swz(row, wn * 8 + 4 + np * 2 + (g >> 1), 9),
                        oB01[mt][2 * np], oB23[mt][2 * np],
                        oB01[mt][2 * np + 1], oB23[mt][2 * np + 1]);
            }
        }
    };

    // phase wrapper: PAIR (readers done) -> full drain -> PAIR (visibility)
    auto phase_sync = [&]() {
        barn(PAIR, 64);
        cp_wait<0>();
        barn(PAIR, 64);
    };

    // ---- prologue ----------------------------------------------------------
    prefetch_gather((int)blockIdx.x, SM_AREAA);
    cp_commit();
    if (tid < 256) {   // W4: 8 rows x 32 chunks
        int n = tid >> 5, c = tid & 31;
        cp16(sb + SM_W4 + (uint32_t)n * 512 + (uint32_t)((c ^ (n & 7)) << 4),
             g_w4i + (size_t)n * 256 + c * 8);
    }
    cp_commit();
    bload0(bufX, 0);                      // (0,X) for first tile
    for (int i = tid; i < 1024; i += 256) {
        int l = i >> 8, n = i & 255;
        const float* p = (l == 0) ? b0 : (l == 1) ? b1 : (l == 2) ? b2 : b3;
        *(float*)(smem + SM_BIAS + i * 4) = p[n];
    }
    if (tid < 3) *(float*)(smem + SM_B4 + tid * 4) = b4[tid];
    if (tid < 128) {   // P chunk 9 (constant zero padding) — written once
        uint4 z; z.x = z.y = z.z = z.w = 0;
        *(uint4*)(smem + SM_P + tid * 160 + 144) = z;
    }
    // FIX: zero ALL 384 pred floats (previous failing kernels missed 256..383)
    for (int i = tid; i < 384; i += 256) ((float*)(smem + SM_PRED))[i] = 0.0f;
    cp_wait<0>();
    __syncthreads();

    uint32_t areaCur = SM_AREAA, areaNxt = SM_AREAB;
    const float* biasB = (const float*)(smem + SM_BIAS);

    // ---- persistent tile loop ----------------------------------------------
    for (int tile = blockIdx.x; tile < NT; tile += gridDim.x) {
        const int next = tile + gridDim.x;

        // phase 0 (0,X): issue (0,Y)->B1, compute B0
        bload0(bufY, 1);
        compute_half<5, true>(P, bufX, biasB + wn * 64, wm, lane, oA01, oA23);
        phase_sync();

        // phase 1 (0,Y): issue (1,X)->B0, compute B1
        bload(bufX, g_w1i, 0);
        compute_half<5, true>(P, bufY, biasB + wn * 64 + 32, wm, lane, oB01, oB23);
        phase_sync();

        // L0 boundary
        barn(GRP, 128);                    // P reads + act reads (prev tile) done
        store_out();
        if (next < NT) { prefetch_gather(next, areaNxt); }
        cp_commit();                       // gather group (may be empty)
        barn(GRP, 128);                    // stores visible

        // phase 2 (1,X): issue (1,Y)->B1, compute B0
        bload(bufY, g_w1i, 1);
        compute_half<16, false>(act, bufX, biasB + 256 + wn * 64, wm, lane, oA01, oA23);
        phase_sync();                      // also retires gather group

        // phase 3 (1,Y): issue (2,X)->B0, compute B1
        bload(bufX, g_w2i, 0);
        compute_half<16, false>(act, bufY, biasB + 256 + wn * 64 + 32, wm, lane, oB01, oB23);
        phase_sync();
        barn(GRP, 128); store_out(); barn(GRP, 128);

        // phase 4 (2,X): issue (2,Y)->B1, compute B0
        bload(bufY, g_w2i, 1);
        compute_half<16, false>(act, bufX, biasB + 512 + wn * 64, wm, lane, oA01, oA23);
        phase_sync();

        // phase 5 (2,Y): issue (3,X)->B0, compute B1
        bload(bufX, g_w3i, 0);
        compute_half<16, false>(act, bufY, biasB + 512 + wn * 64 + 32, wm, lane, oB01, oB23);
        phase_sync();
        barn(GRP, 128); store_out(); barn(GRP, 128);

        // phase 6 (3,X): issue (3,Y)->B1, compute B0
        bload(bufY, g_w3i, 1);
        compute_half<16, false>(act, bufX, biasB + 768 + wn * 64, wm, lane, oA01, oA23);
        phase_sync();

        // phase 7 (3,Y): issue next tile (0,X)->B0, compute B1
        bload0(bufX, 0);
        compute_half<16, false>(act, bufY, biasB + 768 + wn * 64 + 32, wm, lane, oB01, oB23);
        phase_sync();

        // ---- layer 4 from registers: D-frag == A-frag; B from W4 ----
        {
            float a4[4][4];
            #pragma unroll
            for (int mt = 0; mt < 4; mt++)
                #pragma unroll
                for (int u = 0; u < 4; u++) a4[mt][u] = 0.0f;
            uint32_t bfr[4][2];
            #pragma unroll
            for (int j = 0; j < 4; j++)
                ldsm_x2(bfr[j], sb + SM_W4 + swz(lane & 7, (wn * 4 + j) * 2 + ((lane >> 3) & 1), 9));
            #pragma unroll
            for (int mt = 0; mt < 4; mt++) {
                #pragma unroll
                for (int j = 0; j < 2; j++) {
                    uint32_t afr[4] = { oA01[mt][2 * j], oA23[mt][2 * j],
                                        oA01[mt][2 * j + 1], oA23[mt][2 * j + 1] };
                    mma16816(a4[mt], afr, bfr[j]);
                }
                #pragma unroll
                for (int j = 0; j < 2; j++) {
                    uint32_t afr[4] = { oB01[mt][2 * j], oB23[mt][2 * j],
                                        oB01[mt][2 * j + 1], oB23[mt][2 * j + 1] };
                    mma16816(a4[mt], afr, bfr[2 + j]);
                }
            }
            float* pred = (float*)(smem + SM_PRED);
            int t4 = lane & 3, g2 = lane >> 2;
            if (t4 == 0) {
                #pragma unroll
                for (int mt = 0; mt < 4; mt++) {
                    int r = wm * 64 + mt * 16 + g2;
                    atomicAdd(&pred[r * 3 + 0], a4[mt][0]);
                    atomicAdd(&pred[r * 3 + 1], a4[mt][1]);
                    atomicAdd(&pred[(r + 8) * 3 + 0], a4[mt][2]);
                    atomicAdd(&pred[(r + 8) * 3 + 1], a4[mt][3]);
                }
            } else if (t4 == 1) {
                #pragma unroll
                for (int mt = 0; mt < 4; mt++) {
                    int r = wm * 64 + mt * 16 + g2;
                    atomicAdd(&pred[r * 3 + 2], a4[mt][0]);
                    atomicAdd(&pred[(r + 8) * 3 + 2], a4[mt][2]);
                }
            }
        }
        __syncthreads();

        // combine: 32 points (b4 folded in: ensemble weights sum to 1)
        if (tid < 32) {
            const float* PR = (const float*)(smem + SM_PRED);
            const float* AR = (const float*)(smem + areaCur);
            const float* B4 = (const float*)(smem + SM_B4);
            int base = tid * 4;
            float a0 = AR[base], a1 = AR[base + 1], a2 = AR[base + 2], a3 = AR[base + 3];
            float inv = 1.0f / (a0 + a1 + a2 + a3);
            size_t point = (size_t)tile * 32 + tid;
            #pragma unroll
            for (int c = 0; c < 3; c++) {
                float v = PR[(base + 0) * 3 + c] * a3 + PR[(base + 1) * 3 + c] * a2 +
                          PR[(base + 2) * 3 + c] * a1 + PR[(base + 3) * 3 + c] * a0;
                out[point * 3 + c] = v * inv + B4[c];
            }
        }
        __syncthreads();

        // zero own group's pred rows (64 rows * 3 = 192 floats per wm group)
        {
            float* pred = (float*)(smem + SM_PRED);
            int i = tid & 127;
            int base = wm * 192;
            pred[base + i] = 0.0f;
            if (i < 64) pred[base + 128 + i] = 0.0f;
        }
        __syncthreads();               // visibility: P/area gather, pred zero

        uint32_t t = areaCur; areaCur = areaNxt; areaNxt = t;
    }
}

// ============================================================================
// Launch
// ============================================================================
extern "C" void kernel_launch(void* const* d_in, const int* in_sizes, int n_in,
                              void* d_out, int out_size) {
    const float* feat  = (const float*)d_in[0];
    const float* coord = (const float*)d_in[1];
    const float* cell  = (const float*)d_in[2];
    const float* w0 = (const float*)d_in[3];
    const float* b0 = (const float*)d_in[4];
    const float* w1 = (const float*)d_in[5];
    const float* b1 = (const float*)d_in[6];
    const float* w2 = (const float*)d_in[7];
    const float* b2 = (const float*)d_in[8];
    const float* w3 = (const float*)d_in[9];
    const float* b3 = (const float*)d_in[10];
    const float* w4 = (const float*)d_in[11];
    const float* b4 = (const float*)d_in[12];
    float* out = (float*)d_out;

    static int nsm = 0;
    if (nsm == 0) {
        cudaFuncSetAttribute(liif_mlp, cudaFuncAttributeMaxDynamicSharedMemorySize, SMEM_BYTES);
        int dev = 0;
        cudaGetDevice(&dev);
        cudaDeviceGetAttribute(&nsm, cudaDevAttrMultiProcessorCount, dev);
        if (nsm <= 0) nsm = 148;
    }

    prep_all<<<(FEAT_N + WTOT + 255) / 256, 256>>>(feat, w0, w1, w2, w3, w4);
    liif_mlp<<<nsm, 256, SMEM_BYTES>>>(coord, cell, b0, b1, b2, b3, b4, out);
}